// round 1
// baseline (speedup 1.0000x reference)
#include <cuda_runtime.h>
#include <math.h>

// Problem constants
#define BATCH 4096
#define SEQT  256
#define DIN0  128
#define HID   64
#define G3    192   // 3*H, PyTorch gate order r,z,n

// Tiling
#define BB 32       // batch rows per block
#define NT 256      // threads per block (8 warps; warp w owns rows 4w..4w+3)

#define PH 68       // pitch for H-sized rows (64+4)
#define PA 196      // pitch for preactivation buffer

// 256 MB scratch for layer-1 hidden sequence [B, T, H] (static: no allocations allowed)
__device__ float g_h1[(long)BATCH * SEQT * HID];

__device__ __forceinline__ float sigf(float x) {
    return __fdividef(1.0f, 1.0f + __expf(-x));
}
__device__ __forceinline__ float tanhfast(float x) {
    // tanh(x) = 2/(1+exp(-2x)) - 1 ; saturates correctly for |x| large
    return __fdividef(2.0f, 1.0f + __expf(-2.0f * x)) - 1.0f;
}

// One GRU layer as a persistent per-batch-tile scan.
// FIRST: reads x [B,T,DI] from xin, writes h1 sequence to g_h1.
// !FIRST: reads g_h1 as input, and at the end computes out[b] = h_last . Wfc + bfc.
template<int DI, bool FIRST>
__global__ __launch_bounds__(NT, 1)
void gru_kernel(const float* __restrict__ xin,
                const float* __restrict__ Wih,
                const float* __restrict__ Whh,
                const float* __restrict__ bih,
                const float* __restrict__ bhh,
                const float* __restrict__ Wfc,
                const float* __restrict__ bfc,
                float* __restrict__ out)
{
    constexpr int PXL = DI + 4;  // padded pitch for input-dim rows

    extern __shared__ float sm[];
    float* sWih = sm;                     // [G3][PXL]
    float* sWhh = sWih + G3 * PXL;        // [G3][PH]
    float* sX   = sWhh + G3 * PH;         // [BB][PXL]
    float* sH   = sX   + BB * PXL;        // [BB][PH]
    float* sA   = sH   + BB * PH;         // [BB][PA]  r,z,nx preactivations
    float* sAn  = sA   + BB * PA;         // [BB][PH]  n-gate hidden part
    float* sb   = sAn  + BB * PH;         // [2*G3 + HID] biases (+fc weights)

    const int tid = threadIdx.x;
    const int b0  = blockIdx.x * BB;

    // ---- stage weights/biases into SMEM ----
    for (int i = tid; i < G3 * DI; i += NT) {
        int g = i / DI, d = i % DI;
        sWih[g * PXL + d] = Wih[i];
    }
    for (int i = tid; i < G3 * HID; i += NT) {
        int g = i / HID, d = i % HID;
        sWhh[g * PH + d] = Whh[i];
    }
    for (int i = tid; i < G3; i += NT) { sb[i] = bih[i]; sb[G3 + i] = bhh[i]; }
    if (!FIRST) {
        for (int i = tid; i < HID; i += NT) sb[2 * G3 + i] = Wfc[i];
    }
    for (int i = tid; i < BB * PH; i += NT) sH[i] = 0.0f;  // h0 = 0
    __syncthreads();

    const int w  = tid >> 5;   // warp id -> rows 4w..4w+3
    const int cg = tid & 31;   // lane -> gate-cols cg + 32*j, j=0..5
                               // j=0,1: r gate; j=2,3: z gate; j=4,5: n gate

    // hoisted biases: r,z combine b_ih+b_hh; n keeps them separate
    float bA[6], bB2[2];
#pragma unroll
    for (int j = 0; j < 6; j++) {
        int c = cg + 32 * j;
        bA[j] = sb[c] + (j < 4 ? sb[G3 + c] : 0.0f);
    }
    bB2[0] = sb[G3 + cg + 128];
    bB2[1] = sb[G3 + cg + 160];

    // precomputed float4 row pointers (strides 528B/272B == 16B mod 128 -> conflict-free)
    const float4* wi4[6];
    const float4* wh4[6];
#pragma unroll
    for (int j = 0; j < 6; j++) {
        wi4[j] = (const float4*)(sWih + (cg + 32 * j) * PXL);
        wh4[j] = (const float4*)(sWhh + (cg + 32 * j) * PH);
    }
    const float4* xr4[4];
    const float4* hr4[4];
#pragma unroll
    for (int r = 0; r < 4; r++) {
        xr4[r] = (const float4*)(sX + (4 * w + r) * PXL);
        hr4[r] = (const float4*)(sH + (4 * w + r) * PH);
    }

    for (int t = 0; t < SEQT; t++) {
        // ---- load input tile for this timestep ----
        if (FIRST) {
            for (int i = tid; i < BB * DI; i += NT) {
                int rr = i / DI, dd = i % DI;
                sX[rr * PXL + dd] = xin[((long)(b0 + rr) * SEQT + t) * DI + dd];
            }
        } else {
            for (int i = tid; i < BB * HID; i += NT) {
                int rr = i >> 6, dd = i & 63;
                sX[rr * PXL + dd] = g_h1[((long)(b0 + rr) * SEQT + t) * HID + dd];
            }
        }
        __syncthreads();

        // ---- gemm: accA = [x | h] projections for r,z (+x-part of n), accB = h-part of n
        float accA[4][6], accB[4][2];
#pragma unroll
        for (int r = 0; r < 4; r++) {
#pragma unroll
            for (int j = 0; j < 6; j++) accA[r][j] = bA[j];
            accB[r][0] = bB2[0];
            accB[r][1] = bB2[1];
        }

#pragma unroll 4
        for (int k = 0; k < DI / 4; k++) {
            float4 xv[4];
#pragma unroll
            for (int r = 0; r < 4; r++) xv[r] = xr4[r][k];
#pragma unroll
            for (int j = 0; j < 6; j++) {
                float4 wv = wi4[j][k];
#pragma unroll
                for (int r = 0; r < 4; r++) {
                    accA[r][j] += xv[r].x * wv.x + xv[r].y * wv.y
                                + xv[r].z * wv.z + xv[r].w * wv.w;
                }
            }
        }
#pragma unroll 4
        for (int k = 0; k < HID / 4; k++) {
            float4 hv[4];
#pragma unroll
            for (int r = 0; r < 4; r++) hv[r] = hr4[r][k];
#pragma unroll
            for (int j = 0; j < 6; j++) {
                float4 wv = wh4[j][k];
#pragma unroll
                for (int r = 0; r < 4; r++) {
                    float d = hv[r].x * wv.x + hv[r].y * wv.y
                            + hv[r].z * wv.z + hv[r].w * wv.w;
                    if (j < 4) accA[r][j] += d;
                    else       accB[r][j - 4] += d;
                }
            }
        }

        // ---- write preactivations ----
#pragma unroll
        for (int r = 0; r < 4; r++) {
            int row = 4 * w + r;
#pragma unroll
            for (int j = 0; j < 4; j++) sA[row * PA + cg + 32 * j] = accA[r][j];
            sA[row * PA + cg + 128] = accA[r][4];
            sA[row * PA + cg + 160] = accA[r][5];
            sAn[row * PH + cg]      = accB[r][0];
            sAn[row * PH + cg + 32] = accB[r][1];
        }
        __syncthreads();

        // ---- gates + h update (2048 tasks, 8 per thread) ----
#pragma unroll
        for (int i = 0; i < (BB * HID) / NT; i++) {
            int task = tid + NT * i;
            int row = task >> 6, u = task & 63;
            float ar = sA[row * PA + u];
            float az = sA[row * PA + 64 + u];
            float ax = sA[row * PA + 128 + u];
            float ah = sAn[row * PH + u];
            float rg = sigf(ar);
            float zg = sigf(az);
            float ng = tanhfast(ax + rg * ah);
            float hold = sH[row * PH + u];
            float hnew = (1.0f - zg) * ng + zg * hold;
            sH[row * PH + u] = hnew;
            if (FIRST) g_h1[((long)(b0 + row) * SEQT + t) * HID + u] = hnew;
        }
        __syncthreads();
    }

    // ---- final FC on last hidden state (layer 2 only) ----
    if (!FIRST) {
        if (tid < BB) {
            float s = bfc[0];
#pragma unroll
            for (int u = 0; u < HID; u++) s += sH[tid * PH + u] * sb[2 * G3 + u];
            out[b0 + tid] = s;
        }
    }
}

extern "C" void kernel_launch(void* const* d_in, const int* in_sizes, int n_in,
                              void* d_out, int out_size)
{
    const float* x    = (const float*)d_in[0];
    const float* Wih0 = (const float*)d_in[1];
    const float* Whh0 = (const float*)d_in[2];
    const float* bih0 = (const float*)d_in[3];
    const float* bhh0 = (const float*)d_in[4];
    const float* Wih1 = (const float*)d_in[5];
    const float* Whh1 = (const float*)d_in[6];
    const float* bih1 = (const float*)d_in[7];
    const float* bhh1 = (const float*)d_in[8];
    const float* Wfc  = (const float*)d_in[9];
    const float* bfc  = (const float*)d_in[10];
    float* out = (float*)d_out;

    // Shared-memory footprints (floats)
    const size_t sm1 = (size_t)(G3 * (DIN0 + 4) + G3 * PH + BB * (DIN0 + 4)
                       + BB * PH + BB * PA + BB * PH + 2 * G3 + HID) * sizeof(float);
    const size_t sm2 = (size_t)(G3 * (HID + 4) + G3 * PH + BB * (HID + 4)
                       + BB * PH + BB * PA + BB * PH + 2 * G3 + HID) * sizeof(float);

    cudaFuncSetAttribute(gru_kernel<DIN0, true>,
                         cudaFuncAttributeMaxDynamicSharedMemorySize, (int)sm1);
    cudaFuncSetAttribute(gru_kernel<HID, false>,
                         cudaFuncAttributeMaxDynamicSharedMemorySize, (int)sm2);

    gru_kernel<DIN0, true><<<BATCH / BB, NT, sm1>>>(
        x, Wih0, Whh0, bih0, bhh0, nullptr, nullptr, nullptr);
    gru_kernel<HID, false><<<BATCH / BB, NT, sm2>>>(
        nullptr, Wih1, Whh1, bih1, bhh1, Wfc, bfc, out);
}

// round 2
// speedup vs baseline: 1.4897x; 1.4897x over previous
#include <cuda_runtime.h>

// Problem constants
#define BATCH 4096
#define SEQT  256
#define DIN0  128
#define HID   64
#define G3    192   // 3*H, PyTorch gate order r,z,n

// Tiling
#define BB 32       // batch rows per block
#define NT 256      // threads per block; warp w owns rows 4w..4w+3
#define PH 68       // padded pitch for H-sized rows (68 % 32 == 4 -> conflict-free strided rows)

// 256 MB scratch for layer-1 hidden sequence [B, T, H]
__device__ float g_h1[(long)BATCH * SEQT * HID];

typedef unsigned long long u64;

__device__ __forceinline__ void ffma2(u64 &acc, u64 a, u64 b) {
    // packed fp32x2 FMA (Blackwell); acc.{lo,hi} += a.{lo,hi} * b.{lo,hi}
    asm("fma.rn.f32x2 %0, %1, %2, %0;" : "+l"(acc) : "l"(a), "l"(b));
}
__device__ __forceinline__ float lo32(u64 v) { return __uint_as_float((unsigned)v); }
__device__ __forceinline__ float hi32(u64 v) { return __uint_as_float((unsigned)(v >> 32)); }

__device__ __forceinline__ float sigf(float x) {
    return __fdividef(1.0f, 1.0f + __expf(-x));
}
__device__ __forceinline__ float tanhfast(float x) {
    return __fdividef(2.0f, 1.0f + __expf(-2.0f * x)) - 1.0f;
}

// One GRU layer as a persistent per-batch-tile scan.
// FIRST: reads x [B,T,DI], writes h1 sequence to g_h1.
// !FIRST: reads g_h1, and at the end computes out[b] = h_last . Wfc + bfc.
template<int DI, bool FIRST>
__global__ __launch_bounds__(NT, 1)
void gru_kernel(const float* __restrict__ xin,
                const float* __restrict__ Wih,
                const float* __restrict__ Whh,
                const float* __restrict__ bih,
                const float* __restrict__ bhh,
                const float* __restrict__ Wfc,
                const float* __restrict__ bfc,
                float* __restrict__ out)
{
    constexpr int PXL = DI + 4;           // padded input-row pitch (PXL % 32 == 4)
    constexpr int K4X = DI / 4;
    constexpr int K4H = HID / 4;
    constexpr int PFN = (BB * DI) / (4 * NT);  // float4 prefetch loads per thread (4 or 2)

    extern __shared__ float sm[];
    float* sWih = sm;                       // [G3][PXL]
    float* sWhh = sWih + G3 * PXL;          // [G3][PH]
    float* sX   = sWhh + G3 * PH;           // [2][BB][PXL] double buffer
    float* sH   = sX   + 2 * BB * PXL;      // [BB][PH]
    float* sb   = sH   + BB * PH;           // biases (+fc weights)

    const int tid = threadIdx.x;
    const int b0  = blockIdx.x * BB;

    // ---- stage weights/biases into SMEM ----
    for (int i = tid; i < G3 * DI; i += NT) {
        int g = i / DI, d = i % DI;
        sWih[g * PXL + d] = Wih[i];
    }
    for (int i = tid; i < G3 * HID; i += NT) {
        int g = i / HID, d = i % HID;
        sWhh[g * PH + d] = Whh[i];
    }
    for (int i = tid; i < G3; i += NT) { sb[i] = bih[i]; sb[G3 + i] = bhh[i]; }
    if (!FIRST) {
        for (int i = tid; i < HID; i += NT) sb[2 * G3 + i] = Wfc[i];
    }
    for (int i = tid; i < BB * PH; i += NT) sH[i] = 0.0f;  // h0 = 0
    __syncthreads();

    const int w  = tid >> 5;   // warp id -> rows 4w..4w+3
    const int cg = tid & 31;   // lane -> gate cols cg + 32*j, j=0..5 (j 0,1:r  2,3:z  4,5:n)
    const int R0 = 4 * w;

    // hoisted biases: r,z combine b_ih+b_hh; n keeps them separate
    float bA[6], bB2[2];
#pragma unroll
    for (int j = 0; j < 6; j++) {
        int c = cg + 32 * j;
        bA[j] = sb[c] + (j < 4 ? sb[G3 + c] : 0.0f);
    }
    bB2[0] = sb[G3 + cg + 128];
    bB2[1] = sb[G3 + cg + 160];

    // 128-bit views (rows 16B-aligned: PXL,PH multiples of 4)
    const ulonglong2* wi4[6];
    const ulonglong2* wh4[6];
#pragma unroll
    for (int j = 0; j < 6; j++) {
        wi4[j] = (const ulonglong2*)(sWih + (cg + 32 * j) * PXL);
        wh4[j] = (const ulonglong2*)(sWhh + (cg + 32 * j) * PH);
    }
    const ulonglong2* hp4[4];
#pragma unroll
    for (int r = 0; r < 4; r++)
        hp4[r] = (const ulonglong2*)(sH + (R0 + r) * PH);

    // register-resident h for this thread's (row, u) ownership
    float hreg[4][2];
#pragma unroll
    for (int r = 0; r < 4; r++) { hreg[r][0] = 0.0f; hreg[r][1] = 0.0f; }

    const float4* src4 = (const float4*)(FIRST ? xin : g_h1);  // [B,T,DI] row-major

    // ---- prefetch tile t=0 ----
    float4 pf[PFN];
#pragma unroll
    for (int q = 0; q < PFN; q++) {
        int v = tid + NT * q;
        int row = v / K4X, c4 = v % K4X;
        pf[q] = src4[((long)(b0 + row) * SEQT + 0) * K4X + c4];
    }
#pragma unroll
    for (int q = 0; q < PFN; q++) {
        int v = tid + NT * q;
        int row = v / K4X, c4 = v % K4X;
        ((float4*)(sX + row * PXL))[c4] = pf[q];
    }
    __syncthreads();

    for (int t = 0; t < SEQT; t++) {
        const int cur = t & 1;
        const float* sXc = sX + cur * BB * PXL;

        // LDG prefetch for t+1 (latency hidden behind the GEMM)
        if (t + 1 < SEQT) {
#pragma unroll
            for (int q = 0; q < PFN; q++) {
                int v = tid + NT * q;
                int row = v / K4X, c4 = v % K4X;
                pf[q] = src4[((long)(b0 + row) * SEQT + (t + 1)) * K4X + c4];
            }
        }

        // ---- GEMM: packed-K accumulators (lo = even k, hi = odd k) ----
        u64 accA[4][6], accB[4][2];
#pragma unroll
        for (int r = 0; r < 4; r++) {
#pragma unroll
            for (int j = 0; j < 6; j++) accA[r][j] = 0ull;
            accB[r][0] = 0ull; accB[r][1] = 0ull;
        }

        const ulonglong2* xp4[4];
#pragma unroll
        for (int r = 0; r < 4; r++)
            xp4[r] = (const ulonglong2*)(sXc + (R0 + r) * PXL);

#pragma unroll 4
        for (int k = 0; k < K4X; k++) {
            ulonglong2 xv[4];
#pragma unroll
            for (int r = 0; r < 4; r++) xv[r] = xp4[r][k];
#pragma unroll
            for (int j = 0; j < 6; j++) {
                ulonglong2 wv = wi4[j][k];
#pragma unroll
                for (int r = 0; r < 4; r++) {
                    ffma2(accA[r][j], xv[r].x, wv.x);
                    ffma2(accA[r][j], xv[r].y, wv.y);
                }
            }
        }
#pragma unroll 4
        for (int k = 0; k < K4H; k++) {
            ulonglong2 hv[4];
#pragma unroll
            for (int r = 0; r < 4; r++) hv[r] = hp4[r][k];
#pragma unroll
            for (int j = 0; j < 4; j++) {
                ulonglong2 wv = wh4[j][k];
#pragma unroll
                for (int r = 0; r < 4; r++) {
                    ffma2(accA[r][j], hv[r].x, wv.x);
                    ffma2(accA[r][j], hv[r].y, wv.y);
                }
            }
#pragma unroll
            for (int j = 4; j < 6; j++) {
                ulonglong2 wv = wh4[j][k];
#pragma unroll
                for (int r = 0; r < 4; r++) {
                    ffma2(accB[r][j - 4], hv[r].x, wv.x);
                    ffma2(accB[r][j - 4], hv[r].y, wv.y);
                }
            }
        }

        // STS prefetch into the other buffer (safe: consumers passed last barrier)
        if (t + 1 < SEQT) {
            float* sXn = sX + (1 - cur) * BB * PXL;
#pragma unroll
            for (int q = 0; q < PFN; q++) {
                int v = tid + NT * q;
                int row = v / K4X, c4 = v % K4X;
                ((float4*)(sXn + row * PXL))[c4] = pf[q];
            }
        }

        // all lanes of this warp are done reading sH rows R0..R0+3
        __syncwarp();

        // ---- fused gates + h update (this thread owns (row, cg) and (row, cg+32)) ----
#pragma unroll
        for (int r = 0; r < 4; r++) {
            float A0 = bA[0] + lo32(accA[r][0]) + hi32(accA[r][0]);
            float A1 = bA[1] + lo32(accA[r][1]) + hi32(accA[r][1]);
            float A2 = bA[2] + lo32(accA[r][2]) + hi32(accA[r][2]);
            float A3 = bA[3] + lo32(accA[r][3]) + hi32(accA[r][3]);
            float A4 = bA[4] + lo32(accA[r][4]) + hi32(accA[r][4]);
            float A5 = bA[5] + lo32(accA[r][5]) + hi32(accA[r][5]);
            float B0 = bB2[0] + lo32(accB[r][0]) + hi32(accB[r][0]);
            float B1 = bB2[1] + lo32(accB[r][1]) + hi32(accB[r][1]);

            float rg0 = sigf(A0), rg1 = sigf(A1);
            float zg0 = sigf(A2), zg1 = sigf(A3);
            float ng0 = tanhfast(A4 + rg0 * B0);
            float ng1 = tanhfast(A5 + rg1 * B1);
            float h0 = ng0 + zg0 * (hreg[r][0] - ng0);
            float h1 = ng1 + zg1 * (hreg[r][1] - ng1);
            hreg[r][0] = h0; hreg[r][1] = h1;

            sH[(R0 + r) * PH + cg]      = h0;
            sH[(R0 + r) * PH + cg + 32] = h1;
            if (FIRST) {
                long base = ((long)(b0 + R0 + r) * SEQT + t) * HID;
                g_h1[base + cg]      = h0;
                g_h1[base + cg + 32] = h1;
            }
        }
        __syncthreads();
    }

    // ---- final FC on last hidden state (layer 2 only) ----
    if (!FIRST) {
        if (tid < BB) {
            float s = bfc[0];
#pragma unroll
            for (int u = 0; u < HID; u++) s += sH[tid * PH + u] * sb[2 * G3 + u];
            out[b0 + tid] = s;
        }
    }
}

extern "C" void kernel_launch(void* const* d_in, const int* in_sizes, int n_in,
                              void* d_out, int out_size)
{
    const float* x    = (const float*)d_in[0];
    const float* Wih0 = (const float*)d_in[1];
    const float* Whh0 = (const float*)d_in[2];
    const float* bih0 = (const float*)d_in[3];
    const float* bhh0 = (const float*)d_in[4];
    const float* Wih1 = (const float*)d_in[5];
    const float* Whh1 = (const float*)d_in[6];
    const float* bih1 = (const float*)d_in[7];
    const float* bhh1 = (const float*)d_in[8];
    const float* Wfc  = (const float*)d_in[9];
    const float* bfc  = (const float*)d_in[10];
    float* out = (float*)d_out;

    const size_t sm1 = (size_t)(G3 * (DIN0 + 4) + G3 * PH + 2 * BB * (DIN0 + 4)
                       + BB * PH + 2 * G3 + HID) * sizeof(float);
    const size_t sm2 = (size_t)(G3 * (HID + 4) + G3 * PH + 2 * BB * (HID + 4)
                       + BB * PH + 2 * G3 + HID) * sizeof(float);

    cudaFuncSetAttribute(gru_kernel<DIN0, true>,
                         cudaFuncAttributeMaxDynamicSharedMemorySize, (int)sm1);
    cudaFuncSetAttribute(gru_kernel<HID, false>,
                         cudaFuncAttributeMaxDynamicSharedMemorySize, (int)sm2);

    gru_kernel<DIN0, true><<<BATCH / BB, NT, sm1>>>(
        x, Wih0, Whh0, bih0, bhh0, nullptr, nullptr, nullptr);
    gru_kernel<HID, false><<<BATCH / BB, NT, sm2>>>(
        nullptr, Wih1, Whh1, bih1, bhh1, Wfc, bfc, out);
}

// round 4
// speedup vs baseline: 1.7181x; 1.1533x over previous
#include <cuda_runtime.h>
#include <cuda_bf16.h>
#include <stdint.h>

#define BATCH 4096
#define SEQT  256
#define DIN0  128
#define HID   64
#define G3    192
#define MTOT  (BATCH * SEQT)   // 1048576 rows

// Scratch (static: no allocations allowed)
__device__ float g_gx[(long)MTOT * G3];   // 768 MB gate preactivations (reused both layers)
__device__ float g_h1[(long)MTOT * HID];  // 256 MB layer-1 hidden sequence

typedef unsigned long long u64;
typedef unsigned int u32;

// ================================================================= GEMM
// OUT[m][n] = sum_k X[m][k] * W[n][k]  (no bias), split-bf16 3-term via
// mma.sync m16n8k16 (sm_80 PTX path -> HMMA on Blackwell; tcgen05 is not
// available because harness PTX targets compute_103 without the 'a' suffix).
// CTA tile: M=128, N=192. 8 warps as 2(M) x 4(N); warp tile 64x48.

__device__ __forceinline__ void mma16816(float* c, const u32* a, const u32* b) {
    asm volatile(
        "mma.sync.aligned.m16n8k16.row.col.f32.bf16.bf16.f32 "
        "{%0,%1,%2,%3}, {%4,%5,%6,%7}, {%8,%9}, {%0,%1,%2,%3};"
        : "+f"(c[0]), "+f"(c[1]), "+f"(c[2]), "+f"(c[3])
        : "r"(a[0]), "r"(a[1]), "r"(a[2]), "r"(a[3]), "r"(b[0]), "r"(b[1]));
}

// split one fp32 -> (hi bf16, lo bf16), lo = round(x - hi)
__device__ __forceinline__ void split8(const float* v, u32* hp, u32* lp) {
#pragma unroll
    for (int j = 0; j < 4; j++) {
        float a = v[2 * j], b = v[2 * j + 1];
        __nv_bfloat16 ah = __float2bfloat16(a), bh = __float2bfloat16(b);
        float al = a - __bfloat162float(ah);
        float bl = b - __bfloat162float(bh);
        __nv_bfloat16 alb = __float2bfloat16(al), blb = __float2bfloat16(bl);
        hp[j] = ((u32)__bfloat16_as_ushort(ah)) | ((u32)__bfloat16_as_ushort(bh) << 16);
        lp[j] = ((u32)__bfloat16_as_ushort(alb)) | ((u32)__bfloat16_as_ushort(blb) << 16);
    }
}

template<int K>
__global__ __launch_bounds__(256, 1)
void proj_gemm(const float* __restrict__ X,   // [MTOT][K]
               const float* __restrict__ W,   // [G3][K]
               float* __restrict__ OUT)       // [MTOT][G3]
{
    constexpr int P    = K + 8;               // bf16 pitch (byte pitch 2P ≡ 16 mod 256 -> conflict-free)
    constexpr int ASZ  = 128 * P * 2;         // bytes per A buffer
    constexpr int BSZ  = G3 * P * 2;

    extern __shared__ char smem[];
    char* Ah = smem;
    char* Al = Ah + ASZ;
    char* Bh = Al + ASZ;
    char* Bl = Bh + BSZ;

    const int tid = threadIdx.x;
    const int wid = tid >> 5;
    const int lid = tid & 31;
    const long m0 = (long)blockIdx.x * 128;

    // ---- stage + split A: 128 x K ----
    for (int c = tid; c < 128 * (K / 8); c += 256) {
        int row = c / (K / 8), k = (c % (K / 8)) * 8;
        const float4* src = (const float4*)(X + (m0 + row) * K + k);
        float4 v0 = src[0], v1 = src[1];
        float v[8] = {v0.x, v0.y, v0.z, v0.w, v1.x, v1.y, v1.z, v1.w};
        u32 hp[4], lp[4];
        split8(v, hp, lp);
        int byte = (row * P + k) * 2;
        *(uint4*)(Ah + byte) = make_uint4(hp[0], hp[1], hp[2], hp[3]);
        *(uint4*)(Al + byte) = make_uint4(lp[0], lp[1], lp[2], lp[3]);
    }
    // ---- stage + split B: 192 x K ----
    for (int c = tid; c < G3 * (K / 8); c += 256) {
        int row = c / (K / 8), k = (c % (K / 8)) * 8;
        const float4* src = (const float4*)(W + row * K + k);
        float4 v0 = src[0], v1 = src[1];
        float v[8] = {v0.x, v0.y, v0.z, v0.w, v1.x, v1.y, v1.z, v1.w};
        u32 hp[4], lp[4];
        split8(v, hp, lp);
        int byte = (row * P + k) * 2;
        *(uint4*)(Bh + byte) = make_uint4(hp[0], hp[1], hp[2], hp[3]);
        *(uint4*)(Bl + byte) = make_uint4(lp[0], lp[1], lp[2], lp[3]);
    }
    __syncthreads();

    const int mrow = (wid & 1) * 64;      // warp M offset (2 warps in M)
    const int ncol = (wid >> 1) * 48;     // warp N offset (4 warps in N)
    const int g  = lid >> 2;              // group id 0..7
    const int cp = lid & 3;               // pair id 0..3

    float acc[4][6][4];
#pragma unroll
    for (int mt = 0; mt < 4; mt++)
#pragma unroll
        for (int nt = 0; nt < 6; nt++)
#pragma unroll
            for (int q = 0; q < 4; q++) acc[mt][nt][q] = 0.0f;

#pragma unroll
    for (int ks = 0; ks < K / 16; ks++) {
        const int kb = ks * 16;
        u32 ahf[4][4], alf[4][4];
#pragma unroll
        for (int mt = 0; mt < 4; mt++) {
            int r = mrow + mt * 16 + g;
            int c0b = (r * P + kb + 2 * cp) * 2;
            int c1b = ((r + 8) * P + kb + 2 * cp) * 2;
            ahf[mt][0] = *(const u32*)(Ah + c0b);
            ahf[mt][1] = *(const u32*)(Ah + c1b);
            ahf[mt][2] = *(const u32*)(Ah + c0b + 16);
            ahf[mt][3] = *(const u32*)(Ah + c1b + 16);
            alf[mt][0] = *(const u32*)(Al + c0b);
            alf[mt][1] = *(const u32*)(Al + c1b);
            alf[mt][2] = *(const u32*)(Al + c0b + 16);
            alf[mt][3] = *(const u32*)(Al + c1b + 16);
        }
        u32 bhf[6][2], blf[6][2];
#pragma unroll
        for (int nt = 0; nt < 6; nt++) {
            int n = ncol + nt * 8 + g;
            int bb = (n * P + kb + 2 * cp) * 2;
            bhf[nt][0] = *(const u32*)(Bh + bb);
            bhf[nt][1] = *(const u32*)(Bh + bb + 16);
            blf[nt][0] = *(const u32*)(Bl + bb);
            blf[nt][1] = *(const u32*)(Bl + bb + 16);
        }
#pragma unroll
        for (int mt = 0; mt < 4; mt++)
#pragma unroll
            for (int nt = 0; nt < 6; nt++) {
                mma16816(acc[mt][nt], ahf[mt], bhf[nt]);   // AhBh
                mma16816(acc[mt][nt], ahf[mt], blf[nt]);   // AhBl
                mma16816(acc[mt][nt], alf[mt], bhf[nt]);   // AlBh
            }
    }

    // ---- epilogue: direct STG (c0,c1 adjacent cols -> float2) ----
#pragma unroll
    for (int mt = 0; mt < 4; mt++) {
        long r0 = m0 + mrow + mt * 16 + g;
#pragma unroll
        for (int nt = 0; nt < 6; nt++) {
            int col = ncol + nt * 8 + 2 * cp;
            *(float2*)(OUT + r0 * G3 + col)       = make_float2(acc[mt][nt][0], acc[mt][nt][1]);
            *(float2*)(OUT + (r0 + 8) * G3 + col) = make_float2(acc[mt][nt][2], acc[mt][nt][3]);
        }
    }
}

// ============================================================ recurrence
// Slim GRU scan: acc init from precomputed gx (private coalesced LDG), only
// the K=64 hidden projection computed here. No block barriers in the t-loop
// (sH rows are warp-private). BB=16/NT=128 -> grid 256, 2 CTAs/SM.
#define BB 16
#define NT 128
#define PH 68

__device__ __forceinline__ void ffma2(u64 &acc, u64 a, u64 b) {
    asm("fma.rn.f32x2 %0, %1, %2, %0;" : "+l"(acc) : "l"(a), "l"(b));
}
__device__ __forceinline__ float lo32(u64 v) { return __uint_as_float((u32)v); }
__device__ __forceinline__ float hi32(u64 v) { return __uint_as_float((u32)(v >> 32)); }
__device__ __forceinline__ u64 mk2(float lo) { return (u64)__float_as_uint(lo); }

__device__ __forceinline__ float sigf(float x) {
    return __fdividef(1.0f, 1.0f + __expf(-x));
}
__device__ __forceinline__ float tanhfast(float x) {
    return __fdividef(2.0f, 1.0f + __expf(-2.0f * x)) - 1.0f;
}

template<bool FIRST>
__global__ __launch_bounds__(NT, 2)
void gru_recur(const float* __restrict__ GX,   // [MTOT][G3] x-part preactivations (no bias)
               const float* __restrict__ Whh,  // [G3][HID]
               const float* __restrict__ bih,
               const float* __restrict__ bhh,
               const float* __restrict__ Wfc,
               const float* __restrict__ bfc,
               float* __restrict__ hout,       // FIRST: g_h1
               float* __restrict__ out)        // !FIRST: [BATCH]
{
    extern __shared__ float sm[];
    float* sWhh = sm;                 // [G3][PH]
    float* sH   = sWhh + G3 * PH;     // [BB][PH]
    float* sb   = sH + BB * PH;       // 2*G3 biases + HID fc weights

    const int tid = threadIdx.x;
    const int b0  = blockIdx.x * BB;

    for (int i = tid; i < G3 * HID; i += NT) {
        int gg = i / HID, d = i % HID;
        sWhh[gg * PH + d] = Whh[i];
    }
    for (int i = tid; i < G3; i += NT) { sb[i] = bih[i]; sb[G3 + i] = bhh[i]; }
    if (!FIRST) for (int i = tid; i < HID; i += NT) sb[2 * G3 + i] = Wfc[i];
    for (int i = tid; i < BB * PH; i += NT) sH[i] = 0.0f;
    __syncthreads();

    const int w  = tid >> 5;
    const int cg = tid & 31;
    const int R0 = 4 * w;

    float bA[6];
#pragma unroll
    for (int j = 0; j < 6; j++) {
        int c = cg + 32 * j;
        bA[j] = sb[c] + (j < 4 ? sb[G3 + c] : 0.0f);
    }
    float bB2[2] = { sb[G3 + cg + 128], sb[G3 + cg + 160] };

    const ulonglong2* wh4[6];
#pragma unroll
    for (int j = 0; j < 6; j++)
        wh4[j] = (const ulonglong2*)(sWhh + (cg + 32 * j) * PH);
    const ulonglong2* hp4[4];
#pragma unroll
    for (int r = 0; r < 4; r++)
        hp4[r] = (const ulonglong2*)(sH + (R0 + r) * PH);

    const float* gxp[4];
#pragma unroll
    for (int r = 0; r < 4; r++)
        gxp[r] = GX + (long)(b0 + R0 + r) * SEQT * G3 + cg;

    float hreg[4][2];
#pragma unroll
    for (int r = 0; r < 4; r++) { hreg[r][0] = 0.0f; hreg[r][1] = 0.0f; }

    float pf[4][6];
#pragma unroll
    for (int r = 0; r < 4; r++)
#pragma unroll
        for (int j = 0; j < 6; j++)
            pf[r][j] = __ldg(gxp[r] + 32 * j);

    for (int t = 0; t < SEQT; t++) {
        u64 accA[4][6], accB[4][2];
#pragma unroll
        for (int r = 0; r < 4; r++) {
#pragma unroll
            for (int j = 0; j < 6; j++) accA[r][j] = mk2(bA[j] + pf[r][j]);
            accB[r][0] = mk2(bB2[0]);
            accB[r][1] = mk2(bB2[1]);
        }
        if (t + 1 < SEQT) {
            long off = (long)(t + 1) * G3;
#pragma unroll
            for (int r = 0; r < 4; r++)
#pragma unroll
                for (int j = 0; j < 6; j++)
                    pf[r][j] = __ldg(gxp[r] + off + 32 * j);
        }

        __syncwarp();
#pragma unroll 4
        for (int k = 0; k < HID / 4; k++) {
            ulonglong2 hv[4];
#pragma unroll
            for (int r = 0; r < 4; r++) hv[r] = hp4[r][k];
#pragma unroll
            for (int j = 0; j < 4; j++) {
                ulonglong2 wv = wh4[j][k];
#pragma unroll
                for (int r = 0; r < 4; r++) {
                    ffma2(accA[r][j], hv[r].x, wv.x);
                    ffma2(accA[r][j], hv[r].y, wv.y);
                }
            }
#pragma unroll
            for (int j = 4; j < 6; j++) {
                ulonglong2 wv = wh4[j][k];
#pragma unroll
                for (int r = 0; r < 4; r++) {
                    ffma2(accB[r][j - 4], hv[r].x, wv.x);
                    ffma2(accB[r][j - 4], hv[r].y, wv.y);
                }
            }
        }
        __syncwarp();

#pragma unroll
        for (int r = 0; r < 4; r++) {
            float A0 = lo32(accA[r][0]) + hi32(accA[r][0]);
            float A1 = lo32(accA[r][1]) + hi32(accA[r][1]);
            float A2 = lo32(accA[r][2]) + hi32(accA[r][2]);
            float A3 = lo32(accA[r][3]) + hi32(accA[r][3]);
            float A4 = lo32(accA[r][4]) + hi32(accA[r][4]);
            float A5 = lo32(accA[r][5]) + hi32(accA[r][5]);
            float B0 = lo32(accB[r][0]) + hi32(accB[r][0]);
            float B1 = lo32(accB[r][1]) + hi32(accB[r][1]);

            float rg0 = sigf(A0), rg1 = sigf(A1);
            float zg0 = sigf(A2), zg1 = sigf(A3);
            float ng0 = tanhfast(A4 + rg0 * B0);
            float ng1 = tanhfast(A5 + rg1 * B1);
            float h0 = ng0 + zg0 * (hreg[r][0] - ng0);
            float h1 = ng1 + zg1 * (hreg[r][1] - ng1);
            hreg[r][0] = h0; hreg[r][1] = h1;

            sH[(R0 + r) * PH + cg]      = h0;
            sH[(R0 + r) * PH + cg + 32] = h1;
            if (FIRST) {
                long base = ((long)(b0 + R0 + r) * SEQT + t) * HID;
                hout[base + cg]      = h0;
                hout[base + cg + 32] = h1;
            }
        }
    }

    if (!FIRST) {
        __syncthreads();
        if (tid < BB) {
            float s = bfc[0];
#pragma unroll
            for (int u = 0; u < HID; u++) s += sH[tid * PH + u] * sb[2 * G3 + u];
            out[b0 + tid] = s;
        }
    }
}

// ================================================================= host
extern "C" void kernel_launch(void* const* d_in, const int* in_sizes, int n_in,
                              void* d_out, int out_size)
{
    const float* x    = (const float*)d_in[0];
    const float* Wih0 = (const float*)d_in[1];
    const float* Whh0 = (const float*)d_in[2];
    const float* bih0 = (const float*)d_in[3];
    const float* bhh0 = (const float*)d_in[4];
    const float* Wih1 = (const float*)d_in[5];
    const float* Whh1 = (const float*)d_in[6];
    const float* bih1 = (const float*)d_in[7];
    const float* bhh1 = (const float*)d_in[8];
    const float* Wfc  = (const float*)d_in[9];
    const float* bfc  = (const float*)d_in[10];
    float* out = (float*)d_out;

    float *gx, *h1;
    cudaGetSymbolAddress((void**)&gx, g_gx);
    cudaGetSymbolAddress((void**)&h1, g_h1);

    const int smG1 = 2 * (128 * (DIN0 + 8) * 2) + 2 * (G3 * (DIN0 + 8) * 2);  // 174080
    const int smG2 = 2 * (128 * (HID + 8) * 2) + 2 * (G3 * (HID + 8) * 2);    // 92160
    const int smR  = (G3 * PH + BB * PH + 2 * G3 + HID) * (int)sizeof(float);

    cudaFuncSetAttribute(proj_gemm<DIN0>, cudaFuncAttributeMaxDynamicSharedMemorySize, smG1);
    cudaFuncSetAttribute(proj_gemm<HID>,  cudaFuncAttributeMaxDynamicSharedMemorySize, smG2);
    cudaFuncSetAttribute(gru_recur<true>,  cudaFuncAttributeMaxDynamicSharedMemorySize, smR);
    cudaFuncSetAttribute(gru_recur<false>, cudaFuncAttributeMaxDynamicSharedMemorySize, smR);

    proj_gemm<DIN0><<<MTOT / 128, 256, smG1>>>(x, Wih0, gx);
    gru_recur<true><<<BATCH / BB, NT, smR>>>(gx, Whh0, bih0, bhh0, nullptr, nullptr, h1, nullptr);
    proj_gemm<HID><<<MTOT / 128, 256, smG2>>>(h1, Wih1, gx);
    gru_recur<false><<<BATCH / BB, NT, smR>>>(gx, Whh1, bih1, bhh1, Wfc, bfc, nullptr, out);
}

// round 6
// speedup vs baseline: 1.8472x; 1.0752x over previous
#include <cuda_runtime.h>
#include <cuda_bf16.h>
#include <stdint.h>

#define BATCH 4096
#define SEQT  256
#define DIN0  128
#define HID   64
#define G3    192
#define MTOT  (BATCH * SEQT)   // 1048576 rows

// Scratch (static: no allocations allowed)
__device__ float g_gx[(long)MTOT * G3];   // 768 MB gate preactivations (reused both layers)
__device__ float g_h1[(long)MTOT * HID];  // 256 MB layer-1 hidden sequence

typedef unsigned long long u64;
typedef unsigned int u32;

// ================================================================= GEMM
// OUT[m][n] = sum_k X[m][k] * W[n][k]  (no bias), split-bf16 3-term via
// mma.sync m16n8k16 (compute_103 PTX has no tcgen05; this is the HMMA path).
// PERSISTENT: grid fixed; each CTA stages+splits B once, then loops over
// M=64 tiles with register-held A prefetch + double-buffered A smem.
// 8 warps as 2(M) x 4(N); warp tile 32x48.

__device__ __forceinline__ void mma16816(float* c, const u32* a, const u32* b) {
    asm volatile(
        "mma.sync.aligned.m16n8k16.row.col.f32.bf16.bf16.f32 "
        "{%0,%1,%2,%3}, {%4,%5,%6,%7}, {%8,%9}, {%0,%1,%2,%3};"
        : "+f"(c[0]), "+f"(c[1]), "+f"(c[2]), "+f"(c[3])
        : "r"(a[0]), "r"(a[1]), "r"(a[2]), "r"(a[3]), "r"(b[0]), "r"(b[1]));
}

__device__ __forceinline__ u32 packhi(float a, float b) {
    return ((u32)__bfloat16_as_ushort(__float2bfloat16(a)))
         | ((u32)__bfloat16_as_ushort(__float2bfloat16(b)) << 16);
}
__device__ __forceinline__ u32 packlo(float a, float b) {
    float al = a - __bfloat162float(__float2bfloat16(a));
    float bl = b - __bfloat162float(__float2bfloat16(b));
    return ((u32)__bfloat16_as_ushort(__float2bfloat16(al)))
         | ((u32)__bfloat16_as_ushort(__float2bfloat16(bl)) << 16);
}

template<int K>
__global__ __launch_bounds__(256, 1)
void proj_gemm(const float* __restrict__ X,   // [MTOT][K]
               const float* __restrict__ W,   // [G3][K]
               float* __restrict__ OUT)       // [MTOT][G3]
{
    constexpr int P      = K + 8;             // bf16 pitch; byte pitch 2P ≡ 16 mod 256 -> conflict-free
    constexpr int NTILES = MTOT / 64;
    constexpr int ABUF   = 64 * P * 2;        // bytes, one A buffer (hi or lo)
    constexpr int BBUF   = G3 * P * 2;
    // float4s per 64xK tile = 64*K/4 = 16*K; per thread (256) = K/16.
    // (R5 bug: this was K/32 -> half of A stayed uninitialized -> NaN.)
    constexpr int NPF    = K / 16;

    extern __shared__ char smem[];
    char* Bh    = smem;
    char* Bl    = Bh + BBUF;
    char* Abase = Bl + BBUF;                  // [buf(2)][hi,lo]

    const int tid = threadIdx.x;
    const int wid = tid >> 5;
    const int lid = tid & 31;
    const int g   = lid >> 2;                 // 0..7
    const int cp  = lid & 3;                  // 0..3
    const int GRID = gridDim.x;

    // ---- stage + split B once ----
    for (int c = tid; c < G3 * (K / 8); c += 256) {
        int row = c / (K / 8), k = (c % (K / 8)) * 8;
        const float4* src = (const float4*)(W + row * K + k);
        float4 v0 = src[0], v1 = src[1];
        int byte = (row * P + k) * 2;
        *(uint4*)(Bh + byte) = make_uint4(packhi(v0.x, v0.y), packhi(v0.z, v0.w),
                                          packhi(v1.x, v1.y), packhi(v1.z, v1.w));
        *(uint4*)(Bl + byte) = make_uint4(packlo(v0.x, v0.y), packlo(v0.z, v0.w),
                                          packlo(v1.x, v1.y), packlo(v1.z, v1.w));
    }

    const int mrow = (wid & 1) * 32;          // 2 warps in M
    const int ncol = (wid >> 1) * 48;         // 4 warps in N

    // ---- prologue: load + stage A for first tile ----
    float4 pfA[NPF];
    long tile0 = blockIdx.x;
    if (tile0 < NTILES) {
#pragma unroll
        for (int q = 0; q < NPF; q++) {
            int idx = tid + 256 * q;                 // float4 index in 64xK tile
            int row = idx / (K / 4), k = (idx % (K / 4)) * 4;
            pfA[q] = *(const float4*)(X + (tile0 * 64 + row) * K + k);
        }
        char* Ah = Abase;
        char* Al = Abase + ABUF;
#pragma unroll
        for (int q = 0; q < NPF; q++) {
            int idx = tid + 256 * q;
            int row = idx / (K / 4), k = (idx % (K / 4)) * 4;
            float4 v = pfA[q];
            int byte = (row * P + k) * 2;
            *(uint2*)(Ah + byte) = make_uint2(packhi(v.x, v.y), packhi(v.z, v.w));
            *(uint2*)(Al + byte) = make_uint2(packlo(v.x, v.y), packlo(v.z, v.w));
        }
    }
    __syncthreads();

    int it = 0;
    for (long tile = tile0; tile < NTILES; tile += GRID, it++) {
        const long nxt = tile + GRID;
        // prefetch next tile's A into registers (latency hidden by MMAs)
        if (nxt < NTILES) {
#pragma unroll
            for (int q = 0; q < NPF; q++) {
                int idx = tid + 256 * q;
                int row = idx / (K / 4), k = (idx % (K / 4)) * 4;
                pfA[q] = *(const float4*)(X + (nxt * 64 + row) * K + k);
            }
        }

        char* Ah = Abase + (it & 1) * 2 * ABUF;
        char* Al = Ah + ABUF;

        float acc[2][6][4];
#pragma unroll
        for (int mt = 0; mt < 2; mt++)
#pragma unroll
            for (int nt = 0; nt < 6; nt++)
#pragma unroll
                for (int q = 0; q < 4; q++) acc[mt][nt][q] = 0.0f;

#pragma unroll
        for (int ks = 0; ks < K / 16; ks++) {
            const int kb = ks * 16;
            u32 ahf[2][4], alf[2][4];
#pragma unroll
            for (int mt = 0; mt < 2; mt++) {
                int r = mrow + mt * 16 + g;
                int c0b = (r * P + kb + 2 * cp) * 2;
                int c1b = ((r + 8) * P + kb + 2 * cp) * 2;
                ahf[mt][0] = *(const u32*)(Ah + c0b);
                ahf[mt][1] = *(const u32*)(Ah + c1b);
                ahf[mt][2] = *(const u32*)(Ah + c0b + 16);
                ahf[mt][3] = *(const u32*)(Ah + c1b + 16);
                alf[mt][0] = *(const u32*)(Al + c0b);
                alf[mt][1] = *(const u32*)(Al + c1b);
                alf[mt][2] = *(const u32*)(Al + c0b + 16);
                alf[mt][3] = *(const u32*)(Al + c1b + 16);
            }
            u32 bhf[6][2], blf[6][2];
#pragma unroll
            for (int nt = 0; nt < 6; nt++) {
                int n = ncol + nt * 8 + g;
                int bb = (n * P + kb + 2 * cp) * 2;
                bhf[nt][0] = *(const u32*)(Bh + bb);
                bhf[nt][1] = *(const u32*)(Bh + bb + 16);
                blf[nt][0] = *(const u32*)(Bl + bb);
                blf[nt][1] = *(const u32*)(Bl + bb + 16);
            }
#pragma unroll
            for (int mt = 0; mt < 2; mt++)
#pragma unroll
                for (int nt = 0; nt < 6; nt++) {
                    mma16816(acc[mt][nt], ahf[mt], bhf[nt]);   // AhBh
                    mma16816(acc[mt][nt], ahf[mt], blf[nt]);   // AhBl
                    mma16816(acc[mt][nt], alf[mt], bhf[nt]);   // AlBh
                }
        }

        // ---- epilogue: direct STG ----
#pragma unroll
        for (int mt = 0; mt < 2; mt++) {
            long r0 = tile * 64 + mrow + mt * 16 + g;
#pragma unroll
            for (int nt = 0; nt < 6; nt++) {
                int col = ncol + nt * 8 + 2 * cp;
                *(float2*)(OUT + r0 * G3 + col)       = make_float2(acc[mt][nt][0], acc[mt][nt][1]);
                *(float2*)(OUT + (r0 + 8) * G3 + col) = make_float2(acc[mt][nt][2], acc[mt][nt][3]);
            }
        }

        // ---- stage next tile into the other buffer ----
        if (nxt < NTILES) {
            char* nAh = Abase + ((it + 1) & 1) * 2 * ABUF;
            char* nAl = nAh + ABUF;
#pragma unroll
            for (int q = 0; q < NPF; q++) {
                int idx = tid + 256 * q;
                int row = idx / (K / 4), k = (idx % (K / 4)) * 4;
                float4 v = pfA[q];
                int byte = (row * P + k) * 2;
                *(uint2*)(nAh + byte) = make_uint2(packhi(v.x, v.y), packhi(v.z, v.w));
                *(uint2*)(nAl + byte) = make_uint2(packlo(v.x, v.y), packlo(v.z, v.w));
            }
        }
        __syncthreads();
    }
}

// ============================================================ recurrence
// Slim GRU scan: acc init from precomputed gx (private coalesced LDG), only
// the K=64 hidden projection computed here. No block barriers in the t-loop
// (sH rows are warp-private). NT=256, warp owns 2 rows; BB=16 -> grid 256,
// 2 CTAs/SM (forced <=128 regs) = 16 warps/SM.
#define BB 16
#define NT 256
#define PH 68

__device__ __forceinline__ void ffma2(u64 &acc, u64 a, u64 b) {
    asm("fma.rn.f32x2 %0, %1, %2, %0;" : "+l"(acc) : "l"(a), "l"(b));
}
__device__ __forceinline__ float lo32(u64 v) { return __uint_as_float((u32)v); }
__device__ __forceinline__ float hi32(u64 v) { return __uint_as_float((u32)(v >> 32)); }
__device__ __forceinline__ u64 mk2(float lo) { return (u64)__float_as_uint(lo); }

__device__ __forceinline__ float sigf(float x) {
    return __fdividef(1.0f, 1.0f + __expf(-x));
}
__device__ __forceinline__ float tanhfast(float x) {
    return __fdividef(2.0f, 1.0f + __expf(-2.0f * x)) - 1.0f;
}

template<bool FIRST>
__global__ __launch_bounds__(NT, 2)
void gru_recur(const float* __restrict__ GX,   // [MTOT][G3] x-part preactivations (no bias)
               const float* __restrict__ Whh,  // [G3][HID]
               const float* __restrict__ bih,
               const float* __restrict__ bhh,
               const float* __restrict__ Wfc,
               const float* __restrict__ bfc,
               float* __restrict__ hout,       // FIRST: g_h1
               float* __restrict__ out)        // !FIRST: [BATCH]
{
    extern __shared__ float sm[];
    float* sWhh = sm;                 // [G3][PH]
    float* sH   = sWhh + G3 * PH;     // [BB][PH]
    float* sb   = sH + BB * PH;       // 2*G3 biases + HID fc weights

    const int tid = threadIdx.x;
    const int b0  = blockIdx.x * BB;

    for (int i = tid; i < G3 * HID; i += NT) {
        int gg = i / HID, d = i % HID;
        sWhh[gg * PH + d] = Whh[i];
    }
    for (int i = tid; i < G3; i += NT) { sb[i] = bih[i]; sb[G3 + i] = bhh[i]; }
    if (!FIRST) for (int i = tid; i < HID; i += NT) sb[2 * G3 + i] = Wfc[i];
    for (int i = tid; i < BB * PH; i += NT) sH[i] = 0.0f;
    __syncthreads();

    const int w  = tid >> 5;          // 0..7, owns rows 2w, 2w+1
    const int cg = tid & 31;
    const int R0 = 2 * w;

    float bA[6];
#pragma unroll
    for (int j = 0; j < 6; j++) {
        int c = cg + 32 * j;
        bA[j] = sb[c] + (j < 4 ? sb[G3 + c] : 0.0f);
    }
    float bB2[2] = { sb[G3 + cg + 128], sb[G3 + cg + 160] };

    const ulonglong2* wh4[6];
#pragma unroll
    for (int j = 0; j < 6; j++)
        wh4[j] = (const ulonglong2*)(sWhh + (cg + 32 * j) * PH);
    const ulonglong2* hp4[2];
#pragma unroll
    for (int r = 0; r < 2; r++)
        hp4[r] = (const ulonglong2*)(sH + (R0 + r) * PH);

    const float* gxp[2];
#pragma unroll
    for (int r = 0; r < 2; r++)
        gxp[r] = GX + (long)(b0 + R0 + r) * SEQT * G3 + cg;

    float hreg[2][2];
#pragma unroll
    for (int r = 0; r < 2; r++) { hreg[r][0] = 0.0f; hreg[r][1] = 0.0f; }

    float pf[2][6];
#pragma unroll
    for (int r = 0; r < 2; r++)
#pragma unroll
        for (int j = 0; j < 6; j++)
            pf[r][j] = __ldg(gxp[r] + 32 * j);

    for (int t = 0; t < SEQT; t++) {
        u64 accA[2][6], accB[2][2];
#pragma unroll
        for (int r = 0; r < 2; r++) {
#pragma unroll
            for (int j = 0; j < 6; j++) accA[r][j] = mk2(bA[j] + pf[r][j]);
            accB[r][0] = mk2(bB2[0]);
            accB[r][1] = mk2(bB2[1]);
        }
        if (t + 1 < SEQT) {
            long off = (long)(t + 1) * G3;
#pragma unroll
            for (int r = 0; r < 2; r++)
#pragma unroll
                for (int j = 0; j < 6; j++)
                    pf[r][j] = __ldg(gxp[r] + off + 32 * j);
        }

        __syncwarp();
#pragma unroll 4
        for (int k = 0; k < HID / 4; k++) {
            ulonglong2 hv[2];
#pragma unroll
            for (int r = 0; r < 2; r++) hv[r] = hp4[r][k];
#pragma unroll
            for (int j = 0; j < 4; j++) {
                ulonglong2 wv = wh4[j][k];
#pragma unroll
                for (int r = 0; r < 2; r++) {
                    ffma2(accA[r][j], hv[r].x, wv.x);
                    ffma2(accA[r][j], hv[r].y, wv.y);
                }
            }
#pragma unroll
            for (int j = 4; j < 6; j++) {
                ulonglong2 wv = wh4[j][k];
#pragma unroll
                for (int r = 0; r < 2; r++) {
                    ffma2(accB[r][j - 4], hv[r].x, wv.x);
                    ffma2(accB[r][j - 4], hv[r].y, wv.y);
                }
            }
        }
        __syncwarp();

#pragma unroll
        for (int r = 0; r < 2; r++) {
            float A0 = lo32(accA[r][0]) + hi32(accA[r][0]);
            float A1 = lo32(accA[r][1]) + hi32(accA[r][1]);
            float A2 = lo32(accA[r][2]) + hi32(accA[r][2]);
            float A3 = lo32(accA[r][3]) + hi32(accA[r][3]);
            float A4 = lo32(accA[r][4]) + hi32(accA[r][4]);
            float A5 = lo32(accA[r][5]) + hi32(accA[r][5]);
            float B0 = lo32(accB[r][0]) + hi32(accB[r][0]);
            float B1 = lo32(accB[r][1]) + hi32(accB[r][1]);

            float rg0 = sigf(A0), rg1 = sigf(A1);
            float zg0 = sigf(A2), zg1 = sigf(A3);
            float ng0 = tanhfast(A4 + rg0 * B0);
            float ng1 = tanhfast(A5 + rg1 * B1);
            float h0 = ng0 + zg0 * (hreg[r][0] - ng0);
            float h1 = ng1 + zg1 * (hreg[r][1] - ng1);
            hreg[r][0] = h0; hreg[r][1] = h1;

            sH[(R0 + r) * PH + cg]      = h0;
            sH[(R0 + r) * PH + cg + 32] = h1;
            if (FIRST) {
                long base = ((long)(b0 + R0 + r) * SEQT + t) * HID;
                hout[base + cg]      = h0;
                hout[base + cg + 32] = h1;
            }
        }
    }

    if (!FIRST) {
        __syncthreads();
        if (tid < BB) {
            float s = bfc[0];
#pragma unroll
            for (int u = 0; u < HID; u++) s += sH[tid * PH + u] * sb[2 * G3 + u];
            out[b0 + tid] = s;
        }
    }
}

// ================================================================= host
extern "C" void kernel_launch(void* const* d_in, const int* in_sizes, int n_in,
                              void* d_out, int out_size)
{
    const float* x    = (const float*)d_in[0];
    const float* Wih0 = (const float*)d_in[1];
    const float* Whh0 = (const float*)d_in[2];
    const float* bih0 = (const float*)d_in[3];
    const float* bhh0 = (const float*)d_in[4];
    const float* Wih1 = (const float*)d_in[5];
    const float* Whh1 = (const float*)d_in[6];
    const float* bih1 = (const float*)d_in[7];
    const float* bhh1 = (const float*)d_in[8];
    const float* Wfc  = (const float*)d_in[9];
    const float* bfc  = (const float*)d_in[10];
    float* out = (float*)d_out;

    float *gx, *h1;
    cudaGetSymbolAddress((void**)&gx, g_gx);
    cudaGetSymbolAddress((void**)&h1, g_h1);

    // GEMM smem: 2*B + 4*A buffers
    const int smG1 = 2 * (G3 * (DIN0 + 8) * 2) + 4 * (64 * (DIN0 + 8) * 2);   // 174080
    const int smG2 = 2 * (G3 * (HID + 8) * 2)  + 4 * (64 * (HID + 8) * 2);    // 92160
    const int smR  = (G3 * PH + BB * PH + 2 * G3 + HID) * (int)sizeof(float); // 58368

    cudaFuncSetAttribute(proj_gemm<DIN0>, cudaFuncAttributeMaxDynamicSharedMemorySize, smG1);
    cudaFuncSetAttribute(proj_gemm<HID>,  cudaFuncAttributeMaxDynamicSharedMemorySize, smG2);
    cudaFuncSetAttribute(gru_recur<true>,  cudaFuncAttributeMaxDynamicSharedMemorySize, smR);
    cudaFuncSetAttribute(gru_recur<false>, cudaFuncAttributeMaxDynamicSharedMemorySize, smR);

    proj_gemm<DIN0><<<148, 256, smG1>>>(x, Wih0, gx);
    gru_recur<true><<<BATCH / BB, NT, smR>>>(gx, Whh0, bih0, bhh0, nullptr, nullptr, h1, nullptr);
    proj_gemm<HID><<<296, 256, smG2>>>(h1, Wih1, gx);   // 2 CTAs/SM at this smem size
    gru_recur<false><<<BATCH / BB, NT, smR>>>(gx, Whh1, bih1, bhh1, Wfc, bfc, nullptr, out);
}

// round 7
// speedup vs baseline: 3.2277x; 1.7473x over previous
#include <cuda_runtime.h>
#include <cuda_bf16.h>
#include <stdint.h>

#define BATCH 4096
#define SEQT  256
#define DIN0  128
#define HID   64
#define G3    192
#define MTOT  (BATCH * SEQT)   // 1048576 rows

// Scratch (static: no allocations allowed)
__device__ float g_gx[(long)MTOT * G3];   // gate preactivations incl. b_ih (reused both layers)
__device__ float g_h1[(long)MTOT * HID];  // layer-1 hidden sequence

typedef unsigned long long u64;
typedef unsigned int u32;

// ---------------------------------------------------------------- common
__device__ __forceinline__ void mma16816(float* c, const u32* a, const u32* b) {
    asm volatile(
        "mma.sync.aligned.m16n8k16.row.col.f32.bf16.bf16.f32 "
        "{%0,%1,%2,%3}, {%4,%5,%6,%7}, {%8,%9}, {%0,%1,%2,%3};"
        : "+f"(c[0]), "+f"(c[1]), "+f"(c[2]), "+f"(c[3])
        : "r"(a[0]), "r"(a[1]), "r"(a[2]), "r"(a[3]), "r"(b[0]), "r"(b[1]));
}
__device__ __forceinline__ u32 packhi(float a, float b) {
    return ((u32)__bfloat16_as_ushort(__float2bfloat16(a)))
         | ((u32)__bfloat16_as_ushort(__float2bfloat16(b)) << 16);
}
__device__ __forceinline__ u32 packlo(float a, float b) {
    float al = a - __bfloat162float(__float2bfloat16(a));
    float bl = b - __bfloat162float(__float2bfloat16(b));
    return ((u32)__bfloat16_as_ushort(__float2bfloat16(al)))
         | ((u32)__bfloat16_as_ushort(__float2bfloat16(bl)) << 16);
}
__device__ __forceinline__ float sigf(float x) {
    return __fdividef(1.0f, 1.0f + __expf(-x));
}
__device__ __forceinline__ float tanhfast(float x) {
    return __fdividef(2.0f, 1.0f + __expf(-2.0f * x)) - 1.0f;
}

// ================================================================= GEMM
// OUT[m][n] = sum_k X[m][k] * W[n][k] + bias[n], split-bf16 3-term HMMA.
// Persistent; B staged+split once; M=64 tiles, A double-buffered. (passed R6)
template<int K>
__global__ __launch_bounds__(256, 1)
void proj_gemm(const float* __restrict__ X,
               const float* __restrict__ W,
               const float* __restrict__ bias,
               float* __restrict__ OUT)
{
    constexpr int P      = K + 8;
    constexpr int NTILES = MTOT / 64;
    constexpr int ABUF   = 64 * P * 2;
    constexpr int BBUF   = G3 * P * 2;
    constexpr int NPF    = K / 16;            // float4 A-prefetch regs/thread

    extern __shared__ char smem[];
    char* Bh    = smem;
    char* Bl    = Bh + BBUF;
    char* Abase = Bl + BBUF;

    const int tid = threadIdx.x;
    const int wid = tid >> 5;
    const int lid = tid & 31;
    const int g   = lid >> 2;
    const int cp  = lid & 3;
    const int GRID = gridDim.x;

    for (int c = tid; c < G3 * (K / 8); c += 256) {
        int row = c / (K / 8), k = (c % (K / 8)) * 8;
        const float4* src = (const float4*)(W + row * K + k);
        float4 v0 = src[0], v1 = src[1];
        int byte = (row * P + k) * 2;
        *(uint4*)(Bh + byte) = make_uint4(packhi(v0.x, v0.y), packhi(v0.z, v0.w),
                                          packhi(v1.x, v1.y), packhi(v1.z, v1.w));
        *(uint4*)(Bl + byte) = make_uint4(packlo(v0.x, v0.y), packlo(v0.z, v0.w),
                                          packlo(v1.x, v1.y), packlo(v1.z, v1.w));
    }

    const int mrow = (wid & 1) * 32;
    const int ncol = (wid >> 1) * 48;

    // per-lane bias for its columns (c0,c1 and c2,c3 share cols)
    float breg[6][2];
#pragma unroll
    for (int nt = 0; nt < 6; nt++) {
        int col = ncol + nt * 8 + 2 * cp;
        breg[nt][0] = bias[col];
        breg[nt][1] = bias[col + 1];
    }

    float4 pfA[NPF];
    long tile0 = blockIdx.x;
    if (tile0 < NTILES) {
#pragma unroll
        for (int q = 0; q < NPF; q++) {
            int idx = tid + 256 * q;
            int row = idx / (K / 4), k = (idx % (K / 4)) * 4;
            pfA[q] = *(const float4*)(X + (tile0 * 64 + row) * K + k);
        }
        char* Ah = Abase;
        char* Al = Abase + ABUF;
#pragma unroll
        for (int q = 0; q < NPF; q++) {
            int idx = tid + 256 * q;
            int row = idx / (K / 4), k = (idx % (K / 4)) * 4;
            float4 v = pfA[q];
            int byte = (row * P + k) * 2;
            *(uint2*)(Ah + byte) = make_uint2(packhi(v.x, v.y), packhi(v.z, v.w));
            *(uint2*)(Al + byte) = make_uint2(packlo(v.x, v.y), packlo(v.z, v.w));
        }
    }
    __syncthreads();

    int it = 0;
    for (long tile = tile0; tile < NTILES; tile += GRID, it++) {
        const long nxt = tile + GRID;
        if (nxt < NTILES) {
#pragma unroll
            for (int q = 0; q < NPF; q++) {
                int idx = tid + 256 * q;
                int row = idx / (K / 4), k = (idx % (K / 4)) * 4;
                pfA[q] = *(const float4*)(X + (nxt * 64 + row) * K + k);
            }
        }

        char* Ah = Abase + (it & 1) * 2 * ABUF;
        char* Al = Ah + ABUF;

        float acc[2][6][4];
#pragma unroll
        for (int mt = 0; mt < 2; mt++)
#pragma unroll
            for (int nt = 0; nt < 6; nt++)
#pragma unroll
                for (int q = 0; q < 4; q++) acc[mt][nt][q] = 0.0f;

#pragma unroll
        for (int ks = 0; ks < K / 16; ks++) {
            const int kb = ks * 16;
            u32 ahf[2][4], alf[2][4];
#pragma unroll
            for (int mt = 0; mt < 2; mt++) {
                int r = mrow + mt * 16 + g;
                int c0b = (r * P + kb + 2 * cp) * 2;
                int c1b = ((r + 8) * P + kb + 2 * cp) * 2;
                ahf[mt][0] = *(const u32*)(Ah + c0b);
                ahf[mt][1] = *(const u32*)(Ah + c1b);
                ahf[mt][2] = *(const u32*)(Ah + c0b + 16);
                ahf[mt][3] = *(const u32*)(Ah + c1b + 16);
                alf[mt][0] = *(const u32*)(Al + c0b);
                alf[mt][1] = *(const u32*)(Al + c1b);
                alf[mt][2] = *(const u32*)(Al + c0b + 16);
                alf[mt][3] = *(const u32*)(Al + c1b + 16);
            }
            u32 bhf[6][2], blf[6][2];
#pragma unroll
            for (int nt = 0; nt < 6; nt++) {
                int n = ncol + nt * 8 + g;
                int bb = (n * P + kb + 2 * cp) * 2;
                bhf[nt][0] = *(const u32*)(Bh + bb);
                bhf[nt][1] = *(const u32*)(Bh + bb + 16);
                blf[nt][0] = *(const u32*)(Bl + bb);
                blf[nt][1] = *(const u32*)(Bl + bb + 16);
            }
#pragma unroll
            for (int mt = 0; mt < 2; mt++)
#pragma unroll
                for (int nt = 0; nt < 6; nt++) {
                    mma16816(acc[mt][nt], ahf[mt], bhf[nt]);
                    mma16816(acc[mt][nt], ahf[mt], blf[nt]);
                    mma16816(acc[mt][nt], alf[mt], bhf[nt]);
                }
        }

#pragma unroll
        for (int mt = 0; mt < 2; mt++) {
            long r0 = tile * 64 + mrow + mt * 16 + g;
#pragma unroll
            for (int nt = 0; nt < 6; nt++) {
                int col = ncol + nt * 8 + 2 * cp;
                *(float2*)(OUT + r0 * G3 + col) =
                    make_float2(acc[mt][nt][0] + breg[nt][0], acc[mt][nt][1] + breg[nt][1]);
                *(float2*)(OUT + (r0 + 8) * G3 + col) =
                    make_float2(acc[mt][nt][2] + breg[nt][0], acc[mt][nt][3] + breg[nt][1]);
            }
        }

        if (nxt < NTILES) {
            char* nAh = Abase + ((it + 1) & 1) * 2 * ABUF;
            char* nAl = nAh + ABUF;
#pragma unroll
            for (int q = 0; q < NPF; q++) {
                int idx = tid + 256 * q;
                int row = idx / (K / 4), k = (idx % (K / 4)) * 4;
                float4 v = pfA[q];
                int byte = (row * P + k) * 2;
                *(uint2*)(nAh + byte) = make_uint2(packhi(v.x, v.y), packhi(v.z, v.w));
                *(uint2*)(nAl + byte) = make_uint2(packlo(v.x, v.y), packlo(v.z, v.w));
            }
        }
        __syncthreads();
    }
}

// ============================================================ recurrence (HMMA)
// Per CTA: 32 batch rows. 8 warps as 2(M) x 4(N); warp tile m16 x n48.
// W_hh lives in B-fragment REGISTERS (hi/lo split, loaded once from GMEM) ->
// zero per-step weight SMEM traffic. Each step:
//   MMA phase : gh = W_hh . h  (h bf16 hi/lo in SMEM A-tile), 3-term split;
//               D + b_hh staged to SMEM gh buffer.
//   gate phase: thread owns (row = tid>>3, units 8*(tid&7)..+7); h state in regs;
//               writes new h (bf16 hi/lo) back to the A-tile.
// gx includes b_ih (added by proj_gemm); gh includes b_hh.
#define BBR 32
#define NTR 256
#define PAB 144                // A-tile byte pitch (72 bf16); 144 % 128 == 16 -> conflict-free
#define PG  196                // gh float pitch

template<bool FIRST>
__global__ __launch_bounds__(NTR, 1)
void gru_hmma(const float* __restrict__ GX,   // [MTOT][G3] x-part preact + b_ih
              const float* __restrict__ Whh,  // [G3][HID]
              const float* __restrict__ bhh,  // [G3]
              const float* __restrict__ Wfc,
              const float* __restrict__ bfc,
              float* __restrict__ hout,       // FIRST: g_h1
              float* __restrict__ out)        // !FIRST: [BATCH]
{
    extern __shared__ char smemc[];
    char*  sAh = smemc;                        // [32][PAB] bf16 hi
    char*  sAl = sAh + BBR * PAB;              // bf16 lo
    float* sGh = (float*)(sAl + BBR * PAB);    // [32][PG] fp32 gh (incl b_hh)

    const int tid = threadIdx.x;
    const int wid = tid >> 5;
    const int lid = tid & 31;
    const int g   = lid >> 2;
    const int cp  = lid & 3;
    const int b0  = blockIdx.x * BBR;

    const int mrow = (wid & 1) * 16;           // 2 warps in M
    const int ncol = (wid >> 1) * 48;          // 4 warps in N

    // ---- W_hh B-fragments (hi/lo) + b_hh, in registers, loaded once ----
    u32 bh[4][6][2], bl[4][6][2];
    float bhv[6][2];
#pragma unroll
    for (int nt = 0; nt < 6; nt++) {
        int n = ncol + nt * 8 + g;
#pragma unroll
        for (int kc = 0; kc < 4; kc++) {
            int k0 = kc * 16 + 2 * cp;
            float w0 = Whh[n * HID + k0],     w1 = Whh[n * HID + k0 + 1];
            float w2 = Whh[n * HID + k0 + 8], w3 = Whh[n * HID + k0 + 9];
            bh[kc][nt][0] = packhi(w0, w1);  bh[kc][nt][1] = packhi(w2, w3);
            bl[kc][nt][0] = packlo(w0, w1);  bl[kc][nt][1] = packlo(w2, w3);
        }
        int colc = ncol + nt * 8 + 2 * cp;
        bhv[nt][0] = bhh[colc];
        bhv[nt][1] = bhh[colc + 1];
    }

    // ---- gate-side identity: row = tid>>3, consecutive units 8*uc.. ----
    const int grow = tid >> 3;                 // 0..31
    const int uc   = tid & 7;                  // unit block (8 consecutive units)
    const long gxrow0 = ((long)(b0 + grow) * SEQT) * G3 + uc * 8;

    float wfc[8];
    if (!FIRST) {
#pragma unroll
        for (int s = 0; s < 8; s++) wfc[s] = Wfc[uc * 8 + s];
    }
    float hreg[8];
#pragma unroll
    for (int s = 0; s < 8; s++) hreg[s] = 0.0f;

    // zero A tiles (h0 = 0)
    for (int i = tid; i < BBR * PAB / 4; i += NTR) {
        ((u32*)sAh)[i] = 0u;
        ((u32*)sAl)[i] = 0u;
    }
    __syncthreads();

    // prefetch gx for t=0: 3 gates x 8 units = 6 float4
    float4 pf[6];
#pragma unroll
    for (int g3 = 0; g3 < 3; g3++) {
        pf[g3 * 2]     = *(const float4*)(GX + gxrow0 + g3 * 64);
        pf[g3 * 2 + 1] = *(const float4*)(GX + gxrow0 + g3 * 64 + 4);
    }

    for (int t = 0; t < SEQT; t++) {
        // ================= MMA phase: gh = Whh . h =================
        float acc[6][4];
#pragma unroll
        for (int nt = 0; nt < 6; nt++)
#pragma unroll
            for (int q = 0; q < 4; q++) acc[nt][q] = 0.0f;

#pragma unroll
        for (int kc = 0; kc < 4; kc++) {
            const int kb = kc * 16;
            u32 ahf[4], alf[4];
            {
                int r = mrow + g;
                int c0b = r * PAB + (kb + 2 * cp) * 2;
                int c1b = (r + 8) * PAB + (kb + 2 * cp) * 2;
                ahf[0] = *(const u32*)(sAh + c0b);
                ahf[1] = *(const u32*)(sAh + c1b);
                ahf[2] = *(const u32*)(sAh + c0b + 16);
                ahf[3] = *(const u32*)(sAh + c1b + 16);
                alf[0] = *(const u32*)(sAl + c0b);
                alf[1] = *(const u32*)(sAl + c1b);
                alf[2] = *(const u32*)(sAl + c0b + 16);
                alf[3] = *(const u32*)(sAl + c1b + 16);
            }
#pragma unroll
            for (int nt = 0; nt < 6; nt++) {
                mma16816(acc[nt], ahf, bh[kc][nt]);
                mma16816(acc[nt], ahf, bl[kc][nt]);
                mma16816(acc[nt], alf, bh[kc][nt]);
            }
        }
        // stage gh + b_hh to SMEM (D layout validated in proj_gemm epilogue)
#pragma unroll
        for (int nt = 0; nt < 6; nt++) {
            int col = ncol + nt * 8 + 2 * cp;
            *(float2*)(sGh + (mrow + g) * PG + col) =
                make_float2(acc[nt][0] + bhv[nt][0], acc[nt][1] + bhv[nt][1]);
            *(float2*)(sGh + (mrow + g + 8) * PG + col) =
                make_float2(acc[nt][2] + bhv[nt][0], acc[nt][3] + bhv[nt][1]);
        }
        __syncthreads();

        // ================= gate phase =================
        {
            const float* gr = sGh + grow * PG + uc * 8;
            float4 r0 = *(const float4*)(gr);
            float4 r1 = *(const float4*)(gr + 4);
            float4 z0 = *(const float4*)(gr + 64);
            float4 z1 = *(const float4*)(gr + 68);
            float4 n0 = *(const float4*)(gr + 128);
            float4 n1 = *(const float4*)(gr + 132);
            float ghr[8] = {r0.x, r0.y, r0.z, r0.w, r1.x, r1.y, r1.z, r1.w};
            float ghz[8] = {z0.x, z0.y, z0.z, z0.w, z1.x, z1.y, z1.z, z1.w};
            float ghn[8] = {n0.x, n0.y, n0.z, n0.w, n1.x, n1.y, n1.z, n1.w};
            float gxr[8] = {pf[0].x, pf[0].y, pf[0].z, pf[0].w, pf[1].x, pf[1].y, pf[1].z, pf[1].w};
            float gxz[8] = {pf[2].x, pf[2].y, pf[2].z, pf[2].w, pf[3].x, pf[3].y, pf[3].z, pf[3].w};
            float gxn[8] = {pf[4].x, pf[4].y, pf[4].z, pf[4].w, pf[5].x, pf[5].y, pf[5].z, pf[5].w};

            float h[8];
#pragma unroll
            for (int s = 0; s < 8; s++) {
                float rg = sigf(gxr[s] + ghr[s]);
                float zg = sigf(gxz[s] + ghz[s]);
                float ng = tanhfast(gxn[s] + rg * ghn[s]);
                h[s] = ng + zg * (hreg[s] - ng);
                hreg[s] = h[s];
            }
            // write h (bf16 hi/lo) back to A tile
            int abyte = grow * PAB + uc * 16;
            *(uint4*)(sAh + abyte) = make_uint4(packhi(h[0], h[1]), packhi(h[2], h[3]),
                                                packhi(h[4], h[5]), packhi(h[6], h[7]));
            *(uint4*)(sAl + abyte) = make_uint4(packlo(h[0], h[1]), packlo(h[2], h[3]),
                                                packlo(h[4], h[5]), packlo(h[6], h[7]));
            if (FIRST) {
                float* hp = hout + ((long)(b0 + grow) * SEQT + t) * HID + uc * 8;
                *(float4*)(hp)     = make_float4(h[0], h[1], h[2], h[3]);
                *(float4*)(hp + 4) = make_float4(h[4], h[5], h[6], h[7]);
            }
            // prefetch gx for t+1 (latency covered by barrier + next MMA phase)
            if (t + 1 < SEQT) {
                const float* gxn1 = GX + gxrow0 + (long)(t + 1) * G3;
#pragma unroll
                for (int g3 = 0; g3 < 3; g3++) {
                    pf[g3 * 2]     = *(const float4*)(gxn1 + g3 * 64);
                    pf[g3 * 2 + 1] = *(const float4*)(gxn1 + g3 * 64 + 4);
                }
            }
        }
        __syncthreads();
    }

    // ---- final FC (layer 2): reduce 8 threads sharing a row via shuffles ----
    if (!FIRST) {
        float s = 0.0f;
#pragma unroll
        for (int q = 0; q < 8; q++) s += hreg[q] * wfc[q];
        s += __shfl_xor_sync(0xFFFFFFFF, s, 1);
        s += __shfl_xor_sync(0xFFFFFFFF, s, 2);
        s += __shfl_xor_sync(0xFFFFFFFF, s, 4);
        if (uc == 0) out[b0 + grow] = s + bfc[0];
    }
}

// ================================================================= host
extern "C" void kernel_launch(void* const* d_in, const int* in_sizes, int n_in,
                              void* d_out, int out_size)
{
    const float* x    = (const float*)d_in[0];
    const float* Wih0 = (const float*)d_in[1];
    const float* Whh0 = (const float*)d_in[2];
    const float* bih0 = (const float*)d_in[3];
    const float* bhh0 = (const float*)d_in[4];
    const float* Wih1 = (const float*)d_in[5];
    const float* Whh1 = (const float*)d_in[6];
    const float* bih1 = (const float*)d_in[7];
    const float* bhh1 = (const float*)d_in[8];
    const float* Wfc  = (const float*)d_in[9];
    const float* bfc  = (const float*)d_in[10];
    float* out = (float*)d_out;

    float *gx, *h1;
    cudaGetSymbolAddress((void**)&gx, g_gx);
    cudaGetSymbolAddress((void**)&h1, g_h1);

    const int smG1 = 2 * (G3 * (DIN0 + 8) * 2) + 4 * (64 * (DIN0 + 8) * 2);
    const int smG2 = 2 * (G3 * (HID + 8) * 2)  + 4 * (64 * (HID + 8) * 2);
    const int smR  = 2 * BBR * PAB + BBR * PG * 4;   // 34304 B

    cudaFuncSetAttribute(proj_gemm<DIN0>, cudaFuncAttributeMaxDynamicSharedMemorySize, smG1);
    cudaFuncSetAttribute(proj_gemm<HID>,  cudaFuncAttributeMaxDynamicSharedMemorySize, smG2);
    cudaFuncSetAttribute(gru_hmma<true>,  cudaFuncAttributeMaxDynamicSharedMemorySize, smR);
    cudaFuncSetAttribute(gru_hmma<false>, cudaFuncAttributeMaxDynamicSharedMemorySize, smR);

    proj_gemm<DIN0><<<148, 256, smG1>>>(x, Wih0, bih0, gx);
    gru_hmma<true><<<BATCH / BBR, NTR, smR>>>(gx, Whh0, bhh0, nullptr, nullptr, h1, nullptr);
    proj_gemm<HID><<<296, 256, smG2>>>(h1, Wih1, bih1, gx);
    gru_hmma<false><<<BATCH / BBR, NTR, smR>>>(gx, Whh1, bhh1, Wfc, bfc, nullptr, out);
}

// round 8
// speedup vs baseline: 3.3852x; 1.0488x over previous
#include <cuda_runtime.h>
#include <cuda_bf16.h>
#include <stdint.h>

#define BATCH 4096
#define SEQT  256
#define DIN0  128
#define HID   64
#define G3    192
#define MTOT  (BATCH * SEQT)   // 1048576 rows

// Scratch (static: no allocations allowed)
__device__ float g_gx[(long)MTOT * G3];   // gate preactivations incl. b_ih (reused both layers)
__device__ float g_h1[(long)MTOT * HID];  // layer-1 hidden sequence

typedef unsigned long long u64;
typedef unsigned int u32;

// ---------------------------------------------------------------- common
__device__ __forceinline__ void mma16816(float* c, const u32* a, const u32* b) {
    asm volatile(
        "mma.sync.aligned.m16n8k16.row.col.f32.bf16.bf16.f32 "
        "{%0,%1,%2,%3}, {%4,%5,%6,%7}, {%8,%9}, {%0,%1,%2,%3};"
        : "+f"(c[0]), "+f"(c[1]), "+f"(c[2]), "+f"(c[3])
        : "r"(a[0]), "r"(a[1]), "r"(a[2]), "r"(a[3]), "r"(b[0]), "r"(b[1]));
}
__device__ __forceinline__ u32 packhi(float a, float b) {
    return ((u32)__bfloat16_as_ushort(__float2bfloat16(a)))
         | ((u32)__bfloat16_as_ushort(__float2bfloat16(b)) << 16);
}
__device__ __forceinline__ u32 packlo(float a, float b) {
    float al = a - __bfloat162float(__float2bfloat16(a));
    float bl = b - __bfloat162float(__float2bfloat16(b));
    return ((u32)__bfloat16_as_ushort(__float2bfloat16(al)))
         | ((u32)__bfloat16_as_ushort(__float2bfloat16(bl)) << 16);
}
__device__ __forceinline__ float tanha(float x) {
    float y;
    asm("tanh.approx.f32 %0, %1;" : "=f"(y) : "f"(x));
    return y;
}
__device__ __forceinline__ float siga(float x) {       // sigmoid via tanh (1 MUFU)
    return fmaf(0.5f, tanha(0.5f * x), 0.5f);
}

// ================================================================= GEMM
// OUT[m][n] = sum_k X[m][k] * W[n][k] + bias[n], split-bf16 3-term HMMA.
// Persistent; B staged+split once; M=64 tiles, A double-buffered. (passed R6/R7)
template<int K>
__global__ __launch_bounds__(256, 1)
void proj_gemm(const float* __restrict__ X,
               const float* __restrict__ W,
               const float* __restrict__ bias,
               float* __restrict__ OUT)
{
    constexpr int P      = K + 8;
    constexpr int NTILES = MTOT / 64;
    constexpr int ABUF   = 64 * P * 2;
    constexpr int BBUF   = G3 * P * 2;
    constexpr int NPF    = K / 16;

    extern __shared__ char smem[];
    char* Bh    = smem;
    char* Bl    = Bh + BBUF;
    char* Abase = Bl + BBUF;

    const int tid = threadIdx.x;
    const int wid = tid >> 5;
    const int lid = tid & 31;
    const int g   = lid >> 2;
    const int cp  = lid & 3;
    const int GRID = gridDim.x;

    for (int c = tid; c < G3 * (K / 8); c += 256) {
        int row = c / (K / 8), k = (c % (K / 8)) * 8;
        const float4* src = (const float4*)(W + row * K + k);
        float4 v0 = src[0], v1 = src[1];
        int byte = (row * P + k) * 2;
        *(uint4*)(Bh + byte) = make_uint4(packhi(v0.x, v0.y), packhi(v0.z, v0.w),
                                          packhi(v1.x, v1.y), packhi(v1.z, v1.w));
        *(uint4*)(Bl + byte) = make_uint4(packlo(v0.x, v0.y), packlo(v0.z, v0.w),
                                          packlo(v1.x, v1.y), packlo(v1.z, v1.w));
    }

    const int mrow = (wid & 1) * 32;
    const int ncol = (wid >> 1) * 48;

    float breg[6][2];
#pragma unroll
    for (int nt = 0; nt < 6; nt++) {
        int col = ncol + nt * 8 + 2 * cp;
        breg[nt][0] = bias[col];
        breg[nt][1] = bias[col + 1];
    }

    float4 pfA[NPF];
    long tile0 = blockIdx.x;
    if (tile0 < NTILES) {
#pragma unroll
        for (int q = 0; q < NPF; q++) {
            int idx = tid + 256 * q;
            int row = idx / (K / 4), k = (idx % (K / 4)) * 4;
            pfA[q] = *(const float4*)(X + (tile0 * 64 + row) * K + k);
        }
        char* Ah = Abase;
        char* Al = Abase + ABUF;
#pragma unroll
        for (int q = 0; q < NPF; q++) {
            int idx = tid + 256 * q;
            int row = idx / (K / 4), k = (idx % (K / 4)) * 4;
            float4 v = pfA[q];
            int byte = (row * P + k) * 2;
            *(uint2*)(Ah + byte) = make_uint2(packhi(v.x, v.y), packhi(v.z, v.w));
            *(uint2*)(Al + byte) = make_uint2(packlo(v.x, v.y), packlo(v.z, v.w));
        }
    }
    __syncthreads();

    int it = 0;
    for (long tile = tile0; tile < NTILES; tile += GRID, it++) {
        const long nxt = tile + GRID;
        if (nxt < NTILES) {
#pragma unroll
            for (int q = 0; q < NPF; q++) {
                int idx = tid + 256 * q;
                int row = idx / (K / 4), k = (idx % (K / 4)) * 4;
                pfA[q] = *(const float4*)(X + (nxt * 64 + row) * K + k);
            }
        }

        char* Ah = Abase + (it & 1) * 2 * ABUF;
        char* Al = Ah + ABUF;

        float acc[2][6][4];
#pragma unroll
        for (int mt = 0; mt < 2; mt++)
#pragma unroll
            for (int nt = 0; nt < 6; nt++)
#pragma unroll
                for (int q = 0; q < 4; q++) acc[mt][nt][q] = 0.0f;

#pragma unroll
        for (int ks = 0; ks < K / 16; ks++) {
            const int kb = ks * 16;
            u32 ahf[2][4], alf[2][4];
#pragma unroll
            for (int mt = 0; mt < 2; mt++) {
                int r = mrow + mt * 16 + g;
                int c0b = (r * P + kb + 2 * cp) * 2;
                int c1b = ((r + 8) * P + kb + 2 * cp) * 2;
                ahf[mt][0] = *(const u32*)(Ah + c0b);
                ahf[mt][1] = *(const u32*)(Ah + c1b);
                ahf[mt][2] = *(const u32*)(Ah + c0b + 16);
                ahf[mt][3] = *(const u32*)(Ah + c1b + 16);
                alf[mt][0] = *(const u32*)(Al + c0b);
                alf[mt][1] = *(const u32*)(Al + c1b);
                alf[mt][2] = *(const u32*)(Al + c0b + 16);
                alf[mt][3] = *(const u32*)(Al + c1b + 16);
            }
            u32 bhf[6][2], blf[6][2];
#pragma unroll
            for (int nt = 0; nt < 6; nt++) {
                int n = ncol + nt * 8 + g;
                int bb = (n * P + kb + 2 * cp) * 2;
                bhf[nt][0] = *(const u32*)(Bh + bb);
                bhf[nt][1] = *(const u32*)(Bh + bb + 16);
                blf[nt][0] = *(const u32*)(Bl + bb);
                blf[nt][1] = *(const u32*)(Bl + bb + 16);
            }
#pragma unroll
            for (int mt = 0; mt < 2; mt++)
#pragma unroll
                for (int nt = 0; nt < 6; nt++) {
                    mma16816(acc[mt][nt], ahf[mt], bhf[nt]);
                    mma16816(acc[mt][nt], ahf[mt], blf[nt]);
                    mma16816(acc[mt][nt], alf[mt], bhf[nt]);
                }
        }

#pragma unroll
        for (int mt = 0; mt < 2; mt++) {
            long r0 = tile * 64 + mrow + mt * 16 + g;
#pragma unroll
            for (int nt = 0; nt < 6; nt++) {
                int col = ncol + nt * 8 + 2 * cp;
                *(float2*)(OUT + r0 * G3 + col) =
                    make_float2(acc[mt][nt][0] + breg[nt][0], acc[mt][nt][1] + breg[nt][1]);
                *(float2*)(OUT + (r0 + 8) * G3 + col) =
                    make_float2(acc[mt][nt][2] + breg[nt][0], acc[mt][nt][3] + breg[nt][1]);
            }
        }

        if (nxt < NTILES) {
            char* nAh = Abase + ((it + 1) & 1) * 2 * ABUF;
            char* nAl = nAh + ABUF;
#pragma unroll
            for (int q = 0; q < NPF; q++) {
                int idx = tid + 256 * q;
                int row = idx / (K / 4), k = (idx % (K / 4)) * 4;
                float4 v = pfA[q];
                int byte = (row * P + k) * 2;
                *(uint2*)(nAh + byte) = make_uint2(packhi(v.x, v.y), packhi(v.z, v.w));
                *(uint2*)(nAl + byte) = make_uint2(packlo(v.x, v.y), packlo(v.z, v.w));
            }
        }
        __syncthreads();
    }
}

// ============================================================ recurrence (HMMA)
// Per CTA: 32 batch rows split into TWO independent 16-row groups:
//   group 0 = warps 0-3 (rows 0-15),  group 1 = warps 4-7 (rows 16-31).
// Each group: 4 warps as 1(M) x 4(N), warp tile m16 x n48; its own named
// barrier -> the groups' MMA/gate phases interleave on each SMSP (wid%4 puts
// one warp of each group per SMSP). Group 1 is phase-staggered via nanosleep.
// W_hh in B-fragment registers (hi/lo); gates via tanh.approx (3 MUFU/unit).
#define BBR 32
#define NTR 256
#define PAB 144                // A-tile byte pitch; 144 % 128 == 16 -> conflict-free
#define PG  196                // gh float pitch

template<bool FIRST>
__global__ __launch_bounds__(NTR, 1)
void gru_hmma(const float* __restrict__ GX,   // [MTOT][G3] x-part preact + b_ih
              const float* __restrict__ Whh,  // [G3][HID]
              const float* __restrict__ bhh,  // [G3]
              const float* __restrict__ Wfc,
              const float* __restrict__ bfc,
              float* __restrict__ hout,       // FIRST: g_h1
              float* __restrict__ out)        // !FIRST: [BATCH]
{
    extern __shared__ char smemc[];
    char*  sAh = smemc;                        // [32][PAB] bf16 hi
    char*  sAl = sAh + BBR * PAB;              // bf16 lo
    float* sGh = (float*)(sAl + BBR * PAB);    // [32][PG] fp32 gh (incl b_hh)

    const int tid = threadIdx.x;
    const int wid = tid >> 5;
    const int lid = tid & 31;
    const int g   = lid >> 2;
    const int cp  = lid & 3;
    const int b0  = blockIdx.x * BBR;

    const int grp  = wid >> 2;                 // 0 or 1
    const int mrow = grp * 16;                 // group's 16-row base
    const int ncol = (wid & 3) * 48;           // 4 N-warps within group

    // ---- W_hh B-fragments (hi/lo) + b_hh, in registers, loaded once ----
    u32 bh[4][6][2], bl[4][6][2];
    float bhv[6][2];
#pragma unroll
    for (int nt = 0; nt < 6; nt++) {
        int n = ncol + nt * 8 + g;
#pragma unroll
        for (int kc = 0; kc < 4; kc++) {
            int k0 = kc * 16 + 2 * cp;
            float w0 = Whh[n * HID + k0],     w1 = Whh[n * HID + k0 + 1];
            float w2 = Whh[n * HID + k0 + 8], w3 = Whh[n * HID + k0 + 9];
            bh[kc][nt][0] = packhi(w0, w1);  bh[kc][nt][1] = packhi(w2, w3);
            bl[kc][nt][0] = packlo(w0, w1);  bl[kc][nt][1] = packlo(w2, w3);
        }
        int colc = ncol + nt * 8 + 2 * cp;
        bhv[nt][0] = bhh[colc];
        bhv[nt][1] = bhh[colc + 1];
    }

    // ---- gate-side identity (within group): 128 threads own 16 rows x 64 units
    const int gtid = tid & 127;
    const int grow = mrow + (gtid >> 3);       // absolute row 0..31
    const int uc   = gtid & 7;                 // unit block (8 consecutive units)
    const long gxrow0 = ((long)(b0 + grow) * SEQT) * G3 + uc * 8;

    float wfc[8];
    if (!FIRST) {
#pragma unroll
        for (int s = 0; s < 8; s++) wfc[s] = Wfc[uc * 8 + s];
    }
    float hreg[8];
#pragma unroll
    for (int s = 0; s < 8; s++) hreg[s] = 0.0f;

    // zero A tiles (h0 = 0)
    for (int i = tid; i < BBR * PAB / 4; i += NTR) {
        ((u32*)sAh)[i] = 0u;
        ((u32*)sAl)[i] = 0u;
    }
    __syncthreads();

    // prefetch gx for t=0
    float4 pf[6];
#pragma unroll
    for (int g3 = 0; g3 < 3; g3++) {
        pf[g3 * 2]     = *(const float4*)(GX + gxrow0 + g3 * 64);
        pf[g3 * 2 + 1] = *(const float4*)(GX + gxrow0 + g3 * 64 + 4);
    }

    // phase stagger: offset group 1 by ~half a step so MMA bursts of one
    // group overlap gate bursts of the other on each SMSP
    if (grp == 1) __nanosleep(400);

    const u32 barid = grp + 1;                 // named barrier 1 / 2, 128 threads

    for (int t = 0; t < SEQT; t++) {
        // ================= MMA phase: gh = Whh . h =================
        float acc[6][4];
#pragma unroll
        for (int nt = 0; nt < 6; nt++)
#pragma unroll
            for (int q = 0; q < 4; q++) acc[nt][q] = 0.0f;

#pragma unroll
        for (int kc = 0; kc < 4; kc++) {
            const int kb = kc * 16;
            u32 ahf[4], alf[4];
            {
                int r = mrow + g;
                int c0b = r * PAB + (kb + 2 * cp) * 2;
                int c1b = (r + 8) * PAB + (kb + 2 * cp) * 2;
                ahf[0] = *(const u32*)(sAh + c0b);
                ahf[1] = *(const u32*)(sAh + c1b);
                ahf[2] = *(const u32*)(sAh + c0b + 16);
                ahf[3] = *(const u32*)(sAh + c1b + 16);
                alf[0] = *(const u32*)(sAl + c0b);
                alf[1] = *(const u32*)(sAl + c1b);
                alf[2] = *(const u32*)(sAl + c0b + 16);
                alf[3] = *(const u32*)(sAl + c1b + 16);
            }
#pragma unroll
            for (int nt = 0; nt < 6; nt++) {
                mma16816(acc[nt], ahf, bh[kc][nt]);
                mma16816(acc[nt], ahf, bl[kc][nt]);
                mma16816(acc[nt], alf, bh[kc][nt]);
            }
        }
#pragma unroll
        for (int nt = 0; nt < 6; nt++) {
            int col = ncol + nt * 8 + 2 * cp;
            *(float2*)(sGh + (mrow + g) * PG + col) =
                make_float2(acc[nt][0] + bhv[nt][0], acc[nt][1] + bhv[nt][1]);
            *(float2*)(sGh + (mrow + g + 8) * PG + col) =
                make_float2(acc[nt][2] + bhv[nt][0], acc[nt][3] + bhv[nt][1]);
        }
        asm volatile("bar.sync %0, 128;" :: "r"(barid) : "memory");

        // ================= gate phase =================
        {
            const float* gr = sGh + grow * PG + uc * 8;
            float4 r0 = *(const float4*)(gr);
            float4 r1 = *(const float4*)(gr + 4);
            float4 z0 = *(const float4*)(gr + 64);
            float4 z1 = *(const float4*)(gr + 68);
            float4 n0 = *(const float4*)(gr + 128);
            float4 n1 = *(const float4*)(gr + 132);
            float ghr[8] = {r0.x, r0.y, r0.z, r0.w, r1.x, r1.y, r1.z, r1.w};
            float ghz[8] = {z0.x, z0.y, z0.z, z0.w, z1.x, z1.y, z1.z, z1.w};
            float ghn[8] = {n0.x, n0.y, n0.z, n0.w, n1.x, n1.y, n1.z, n1.w};
            float gxr[8] = {pf[0].x, pf[0].y, pf[0].z, pf[0].w, pf[1].x, pf[1].y, pf[1].z, pf[1].w};
            float gxz[8] = {pf[2].x, pf[2].y, pf[2].z, pf[2].w, pf[3].x, pf[3].y, pf[3].z, pf[3].w};
            float gxn[8] = {pf[4].x, pf[4].y, pf[4].z, pf[4].w, pf[5].x, pf[5].y, pf[5].z, pf[5].w};

            float h[8];
#pragma unroll
            for (int s = 0; s < 8; s++) {
                float rg = siga(gxr[s] + ghr[s]);
                float zg = siga(gxz[s] + ghz[s]);
                float ng = tanha(gxn[s] + rg * ghn[s]);
                h[s] = ng + zg * (hreg[s] - ng);
                hreg[s] = h[s];
            }
            int abyte = grow * PAB + uc * 16;
            *(uint4*)(sAh + abyte) = make_uint4(packhi(h[0], h[1]), packhi(h[2], h[3]),
                                                packhi(h[4], h[5]), packhi(h[6], h[7]));
            *(uint4*)(sAl + abyte) = make_uint4(packlo(h[0], h[1]), packlo(h[2], h[3]),
                                                packlo(h[4], h[5]), packlo(h[6], h[7]));
            if (FIRST) {
                float* hp = hout + ((long)(b0 + grow) * SEQT + t) * HID + uc * 8;
                *(float4*)(hp)     = make_float4(h[0], h[1], h[2], h[3]);
                *(float4*)(hp + 4) = make_float4(h[4], h[5], h[6], h[7]);
            }
            if (t + 1 < SEQT) {
                const float* gxn1 = GX + gxrow0 + (long)(t + 1) * G3;
#pragma unroll
                for (int g3 = 0; g3 < 3; g3++) {
                    pf[g3 * 2]     = *(const float4*)(gxn1 + g3 * 64);
                    pf[g3 * 2 + 1] = *(const float4*)(gxn1 + g3 * 64 + 4);
                }
            }
        }
        asm volatile("bar.sync %0, 128;" :: "r"(barid) : "memory");
    }

    // ---- final FC (layer 2): 8 consecutive threads share a row ----
    if (!FIRST) {
        float s = 0.0f;
#pragma unroll
        for (int q = 0; q < 8; q++) s += hreg[q] * wfc[q];
        s += __shfl_xor_sync(0xFFFFFFFF, s, 1);
        s += __shfl_xor_sync(0xFFFFFFFF, s, 2);
        s += __shfl_xor_sync(0xFFFFFFFF, s, 4);
        if (uc == 0) out[b0 + grow] = s + bfc[0];
    }
}

// ================================================================= host
extern "C" void kernel_launch(void* const* d_in, const int* in_sizes, int n_in,
                              void* d_out, int out_size)
{
    const float* x    = (const float*)d_in[0];
    const float* Wih0 = (const float*)d_in[1];
    const float* Whh0 = (const float*)d_in[2];
    const float* bih0 = (const float*)d_in[3];
    const float* bhh0 = (const float*)d_in[4];
    const float* Wih1 = (const float*)d_in[5];
    const float* Whh1 = (const float*)d_in[6];
    const float* bih1 = (const float*)d_in[7];
    const float* bhh1 = (const float*)d_in[8];
    const float* Wfc  = (const float*)d_in[9];
    const float* bfc  = (const float*)d_in[10];
    float* out = (float*)d_out;

    float *gx, *h1;
    cudaGetSymbolAddress((void**)&gx, g_gx);
    cudaGetSymbolAddress((void**)&h1, g_h1);

    const int smG1 = 2 * (G3 * (DIN0 + 8) * 2) + 4 * (64 * (DIN0 + 8) * 2);
    const int smG2 = 2 * (G3 * (HID + 8) * 2)  + 4 * (64 * (HID + 8) * 2);
    const int smR  = 2 * BBR * PAB + BBR * PG * 4;

    cudaFuncSetAttribute(proj_gemm<DIN0>, cudaFuncAttributeMaxDynamicSharedMemorySize, smG1);
    cudaFuncSetAttribute(proj_gemm<HID>,  cudaFuncAttributeMaxDynamicSharedMemorySize, smG2);
    cudaFuncSetAttribute(gru_hmma<true>,  cudaFuncAttributeMaxDynamicSharedMemorySize, smR);
    cudaFuncSetAttribute(gru_hmma<false>, cudaFuncAttributeMaxDynamicSharedMemorySize, smR);

    proj_gemm<DIN0><<<148, 256, smG1>>>(x, Wih0, bih0, gx);
    gru_hmma<true><<<BATCH / BBR, NTR, smR>>>(gx, Whh0, bhh0, nullptr, nullptr, h1, nullptr);
    proj_gemm<HID><<<296, 256, smG2>>>(h1, Wih1, bih1, gx);
    gru_hmma<false><<<BATCH / BBR, NTR, smR>>>(gx, Whh1, bhh1, Wfc, bfc, nullptr, out);
}